// round 10
// baseline (speedup 1.0000x reference)
#include <cuda_runtime.h>
#include <cuda_bf16.h>
#include <math.h>

// ---------------------------------------------------------------------------
// MoE router (TOP_K=2, N_EXP=8), single persistent kernel.
// Output (float32): [0..8) used_capacity | [8..8+R) cb_weight | [8+R..8+2R) sec_mask
//   where R = N*8*C.
//
// Grid = 148 CTAs x 1024 threads, one CTA per SM -> all co-resident, so
// device-side spin counters are safe inside one launch.
//   CTA 1..147: warps 0..13  = router (2 tokens/warp, smem w_g)
//               warps 14..31 = zero-fill of the 336MB output (float4 stream)
//   CTA 0     : waits router-done -> ordered rank scan -> waits fill-done
//               -> scatter nonzeros + used_capacity.
// Counters use release(fence)+atomicAdd / spin+acquire(fence); the single
// waiter subtracts the target after observing it, so replays start at zero.
// ---------------------------------------------------------------------------

#define N_EXP 8
#define MAXN 65536
#define GRID 148
#define BLOCK 1024
#define RW_PER_CTA 14              // router warps per worker CTA
#define FW_PER_CTA 18              // fill warps per worker CTA
#define R_TARGET ((GRID - 1) * RW_PER_CTA)   // 2058
#define F_TARGET ((GRID - 1) * FW_PER_CTA)   // 2646

__device__ int          g_eidx[2 * MAXN];
__device__ float        g_pval[2 * MAXN];
__device__ int          g_rank[2 * MAXN];
__device__ unsigned int g_done_router;   // zero-init; self-resetting
__device__ unsigned int g_done_fill;     // zero-init; self-resetting

__global__ void __launch_bounds__(BLOCK, 1) router_fused_kernel(
    const float* __restrict__ x, const float* __restrict__ w_g,
    float* __restrict__ out, int N, int C, long long out_elems)
{
    __shared__ float4 ws[N_EXP * 256];          // 32KB w_g (D=1024)
    __shared__ int warpcnt[N_EXP][32];
    __shared__ int basesh[N_EXP][32];
    __shared__ int running[N_EXP];

    const int tid  = threadIdx.x;
    const int warp = tid >> 5;
    const int lane = tid & 31;
    const int b    = blockIdx.x;

    const long long rowsC     = (long long)N * N_EXP * (long long)C;
    const long long fillF4    = (out_elems - 8) >> 2;   // float4 count
    float4* const   fill4     = reinterpret_cast<float4*>(out + 8);

    if (b != 0) {
        // ---- stage w_g into shared (all 32 warps help) ----
        const float4* wg4 = reinterpret_cast<const float4*>(w_g);
#pragma unroll
        for (int r = 0; r < 2; r++)
            ws[r * BLOCK + tid] = wg4[r * BLOCK + tid];
        __syncthreads();

        if (warp < RW_PER_CTA) {
            // =============== ROUTER WARPS: 2 tokens per warp ===============
            const int rw_total = R_TARGET;               // 2058 router warps
            const int rw = (b - 1) * RW_PER_CTA + warp;

            for (int tok0 = rw * 2; tok0 < N; tok0 += rw_total * 2) {
                const float4* x4 =
                    reinterpret_cast<const float4*>(x) + (size_t)tok0 * 256;
                const bool full = (tok0 + 1) < N;

                float acc[2][N_EXP];
#pragma unroll
                for (int t = 0; t < 2; t++)
#pragma unroll
                    for (int e = 0; e < N_EXP; e++) acc[t][e] = 0.0f;

#pragma unroll
                for (int j = 0; j < 8; j++) {
                    float4 xv[2];
#pragma unroll
                    for (int t = 0; t < 2; t++)
                        xv[t] = (full || (tok0 + t) < N)
                              ? x4[t * 256 + j * 32 + lane]
                              : make_float4(0.f, 0.f, 0.f, 0.f);
#pragma unroll
                    for (int e = 0; e < N_EXP; e++) {
                        float4 wv = ws[e * 256 + j * 32 + lane];
#pragma unroll
                        for (int t = 0; t < 2; t++)
                            acc[t][e] += xv[t].x * wv.x + xv[t].y * wv.y +
                                         xv[t].z * wv.z + xv[t].w * wv.w;
                    }
                }

#pragma unroll
                for (int off = 16; off > 0; off >>= 1)
#pragma unroll
                    for (int t = 0; t < 2; t++)
#pragma unroll
                        for (int e = 0; e < N_EXP; e++)
                            acc[t][e] += __shfl_xor_sync(0xFFFFFFFFu,
                                                         acc[t][e], off);

                if (lane < 2) {
                    const int t = lane;
                    const int token = tok0 + t;
                    if (token < N) {
                        float a[N_EXP];
#pragma unroll
                        for (int e = 0; e < N_EXP; e++) a[e] = acc[t][e];

                        int e0 = 0; float b0 = a[0];
#pragma unroll
                        for (int e = 1; e < N_EXP; e++)
                            if (a[e] > b0) { b0 = a[e]; e0 = e; }
                        int e1 = (e0 == 0) ? 1 : 0; float b1 = a[e1];
#pragma unroll
                        for (int e = 0; e < N_EXP; e++)
                            if (e != e0 && a[e] > b1) { b1 = a[e]; e1 = e; }

                        float sum = 0.0f;
#pragma unroll
                        for (int e = 0; e < N_EXP; e++)
                            sum += expf(a[e] - b0);
                        float inv = 1.0f / sum;

                        g_eidx[token]     = e0;
                        g_eidx[N + token] = e1;
                        g_pval[token]     = inv;
                        g_pval[N + token] = expf(b1 - b0) * inv;
                    }
                }
            }
            __syncwarp();
            if (lane == 0) {
                __threadfence();
                atomicAdd(&g_done_router, 1u);
            }
        } else {
            // =============== FILL WARPS: zero the output ===============
            const int  fw      = (b - 1) * FW_PER_CTA + (warp - RW_PER_CTA);
            const long long per = (fillF4 + F_TARGET - 1) / F_TARGET;
            long long lo = (long long)fw * per;
            long long hi = lo + per; if (hi > fillF4) hi = fillF4;
            const float4 z = make_float4(0.f, 0.f, 0.f, 0.f);
            for (long long i = lo + lane; i < hi; i += 32)
                fill4[i] = z;
            __syncwarp();
            if (lane == 0) {
                __threadfence();
                atomicAdd(&g_done_fill, 1u);
            }
        }
        return;
    }

    // ======================= CTA 0: rank then scatter =======================
    if (tid < N_EXP) running[tid] = 0;

    // ---- wait for all router warps ----
    if (tid == 0) {
        while (atomicAdd(&g_done_router, 0u) < (unsigned)R_TARGET) { }
        atomicSub(&g_done_router, (unsigned)R_TARGET);   // reset for replay
        __threadfence();
    }
    __syncthreads();

    // ---- ordered per-expert rank scan (k-major, token order) ----
    const int total = 2 * N;
    const int rounds = (total + BLOCK - 1) / BLOCK;
    for (int rd = 0; rd < rounds; rd++) {
        const int i = rd * BLOCK + tid;
        const int e = (i < total) ? g_eidx[i] : -1;

        if (tid < N_EXP * 32) ((int*)warpcnt)[tid] = 0;
        __syncthreads();

        unsigned m = __match_any_sync(0xFFFFFFFFu, e);
        int lrank  = __popc(m & ((1u << lane) - 1u));
        int leader = __ffs(m) - 1;
        if (e >= 0 && lane == leader)
            warpcnt[e][warp] = __popc(m);
        __syncthreads();

        if (warp < N_EXP) {
            int runv = running[warp];
            int v = warpcnt[warp][lane];
            int s = v;
#pragma unroll
            for (int off = 1; off < 32; off <<= 1) {
                int u = __shfl_up_sync(0xFFFFFFFFu, s, off);
                if (lane >= off) s += u;
            }
            basesh[warp][lane] = runv + s - v;
            if (lane == 31) running[warp] = runv + s;
        }
        __syncthreads();

        if (e >= 0)
            g_rank[i] = basesh[e][warp] + lrank;
        __syncthreads();
    }

    // used_capacity lives outside the fill region — write now.
    if (tid < N_EXP) {
        int uc = running[tid];
        if (uc > C) uc = C;
        out[tid] = (float)uc;
    }

    // ---- wait for all fill warps, then scatter ----
    if (tid == 0) {
        while (atomicAdd(&g_done_fill, 0u) < (unsigned)F_TARGET) { }
        atomicSub(&g_done_fill, (unsigned)F_TARGET);     // reset for replay
        __threadfence();
    }
    __syncthreads();

    // tail floats not covered by float4 fill (none when C is even, but safe)
    {
        long long done = 8 + (fillF4 << 2);
        for (long long i = done + tid; i < out_elems; i += BLOCK)
            out[i] = 0.0f;
    }

    for (int i = tid; i < total; i += BLOCK) {
        int r = g_rank[i];
        if (r < C) {
            int e = g_eidx[i];
            int k = (i >= N) ? 1 : 0;
            int n = i - k * N;
            long long pos = ((long long)n * N_EXP + e) * (long long)C + r;
            out[8 + pos]         = g_pval[i];
            out[8 + rowsC + pos] = 1.0f;
        }
    }
}

// ---------------------------------------------------------------------------
extern "C" void kernel_launch(void* const* d_in, const int* in_sizes, int n_in,
                              void* d_out, int out_size)
{
    const float* x   = (const float*)d_in[0];
    const float* w_g = (const float*)d_in[1];
    float* out = (float*)d_out;

    const int D = in_sizes[1] / N_EXP;   // 1024
    const int N = in_sizes[0] / D;       // 4096 tokens

    int C = (int)floorf(2.0f * 1.25f * (float)N / (float)N_EXP);
    C += (C & 1);
    if (C < 4) C = 4;

    router_fused_kernel<<<GRID, BLOCK>>>(x, w_g, out, N, C,
                                         (long long)out_size);
}

// round 11
// speedup vs baseline: 1.0069x; 1.0069x over previous
#include <cuda_runtime.h>
#include <cuda_bf16.h>
#include <math.h>

// ---------------------------------------------------------------------------
// MoE router (TOP_K=2, N_EXP=8), single persistent fused kernel.
// Output (float32): [0..8) used_capacity | [8..8+R) cb_weight | [8+R..8+2R) sec_mask
//   where R = N*8*C.
//
// Grid = 148 CTAs x 1024 threads, one CTA per SM (co-resident => device-side
// spin counters are safe).
//   CTA 1..147: warps 0..13  = router (2 tokens/warp, smem w_g)
//               warps 14..31 = zero-fill, GRID-STRIDE interleaved (R10's
//                              per-warp chunking thrashed the TLB: 2646 live
//                              pages >> 128-entry reach -> 3.3 TB/s; the
//                              interleave keeps a ~5MB rolling window).
//   CTA 0     : spin-join router -> ordered rank scan -> spin-join fill
//               -> scatter nonzeros + used_capacity.
// Counters: release-fence + atomicAdd; single waiter subtracts the target
// after observing it, so graph replays always start from zero.
// ---------------------------------------------------------------------------

#define N_EXP 8
#define MAXN 65536
#define GRID 148
#define BLOCK 1024
#define RW_PER_CTA 14              // router warps per worker CTA
#define FW_PER_CTA 18              // fill warps per worker CTA
#define R_TARGET ((GRID - 1) * RW_PER_CTA)          // 2058
#define F_TARGET ((GRID - 1) * FW_PER_CTA)          // 2646
#define F_THREADS ((long long)F_TARGET * 32)        // 84672 fill threads

__device__ int          g_eidx[2 * MAXN];
__device__ float        g_pval[2 * MAXN];
__device__ int          g_rank[2 * MAXN];
__device__ unsigned int g_done_router;   // zero-init; self-resetting
__device__ unsigned int g_done_fill;     // zero-init; self-resetting

__global__ void __launch_bounds__(BLOCK, 1) router_fused_kernel(
    const float* __restrict__ x, const float* __restrict__ w_g,
    float* __restrict__ out, int N, int C, long long out_elems)
{
    __shared__ float4 ws[N_EXP * 256];          // 32KB w_g (D=1024)
    __shared__ int warpcnt[N_EXP][32];
    __shared__ int basesh[N_EXP][32];
    __shared__ int running[N_EXP];

    const int tid  = threadIdx.x;
    const int warp = tid >> 5;
    const int lane = tid & 31;
    const int b    = blockIdx.x;

    const long long rowsC  = (long long)N * N_EXP * (long long)C;
    const long long fillF4 = (out_elems - 8) >> 2;       // float4 count
    float4* const   fill4  = reinterpret_cast<float4*>(out + 8);

    if (b != 0) {
        if (warp >= RW_PER_CTA) {
            // ========== FILL WARPS: grid-stride interleaved zeroing ==========
            const long long ftid =
                (long long)(b - 1) * FW_PER_CTA * 32 +
                (long long)(warp - RW_PER_CTA) * 32 + lane;
            const float4 z = make_float4(0.f, 0.f, 0.f, 0.f);

            long long i = ftid;
            const long long step4 = 4 * F_THREADS;
            for (; i + 3 * F_THREADS < fillF4; i += step4) {
                fill4[i]                 = z;
                fill4[i + F_THREADS]     = z;
                fill4[i + 2 * F_THREADS] = z;
                fill4[i + 3 * F_THREADS] = z;
            }
            for (; i < fillF4; i += F_THREADS)
                fill4[i] = z;

            __syncwarp();
            if (lane == 0) {
                __threadfence();
                atomicAdd(&g_done_fill, 1u);
            }
            return;
        }

        // ============== ROUTER WARPS: 2 tokens per warp ==============
        // stage w_g into shared (router warps only: 14*32=448 threads)
        const float4* wg4 = reinterpret_cast<const float4*>(w_g);
        const int rt = warp * 32 + lane;                 // 0..447
        for (int idx = rt; idx < N_EXP * 256; idx += RW_PER_CTA * 32)
            ws[idx] = wg4[idx];
        // router warps sync among themselves via named barrier 1
        asm volatile("bar.sync 1, %0;" :: "r"(RW_PER_CTA * 32) : "memory");

        const int rw_total = R_TARGET;
        const int rw = (b - 1) * RW_PER_CTA + warp;

        for (int tok0 = rw * 2; tok0 < N; tok0 += rw_total * 2) {
            const float4* x4 =
                reinterpret_cast<const float4*>(x) + (size_t)tok0 * 256;
            const bool full = (tok0 + 1) < N;

            float acc[2][N_EXP];
#pragma unroll
            for (int t = 0; t < 2; t++)
#pragma unroll
                for (int e = 0; e < N_EXP; e++) acc[t][e] = 0.0f;

#pragma unroll
            for (int j = 0; j < 8; j++) {
                float4 xv[2];
#pragma unroll
                for (int t = 0; t < 2; t++)
                    xv[t] = (full || (tok0 + t) < N)
                          ? x4[t * 256 + j * 32 + lane]
                          : make_float4(0.f, 0.f, 0.f, 0.f);
#pragma unroll
                for (int e = 0; e < N_EXP; e++) {
                    float4 wv = ws[e * 256 + j * 32 + lane];
#pragma unroll
                    for (int t = 0; t < 2; t++)
                        acc[t][e] += xv[t].x * wv.x + xv[t].y * wv.y +
                                     xv[t].z * wv.z + xv[t].w * wv.w;
                }
            }

#pragma unroll
            for (int off = 16; off > 0; off >>= 1)
#pragma unroll
                for (int t = 0; t < 2; t++)
#pragma unroll
                    for (int e = 0; e < N_EXP; e++)
                        acc[t][e] += __shfl_xor_sync(0xFFFFFFFFu,
                                                     acc[t][e], off);

            if (lane < 2) {
                const int t = lane;
                const int token = tok0 + t;
                if (token < N) {
                    float a[N_EXP];
#pragma unroll
                    for (int e = 0; e < N_EXP; e++) a[e] = acc[t][e];

                    int e0 = 0; float b0 = a[0];
#pragma unroll
                    for (int e = 1; e < N_EXP; e++)
                        if (a[e] > b0) { b0 = a[e]; e0 = e; }
                    int e1 = (e0 == 0) ? 1 : 0; float b1 = a[e1];
#pragma unroll
                    for (int e = 0; e < N_EXP; e++)
                        if (e != e0 && a[e] > b1) { b1 = a[e]; e1 = e; }

                    float sum = 0.0f;
#pragma unroll
                    for (int e = 0; e < N_EXP; e++)
                        sum += expf(a[e] - b0);
                    float inv = 1.0f / sum;

                    g_eidx[token]     = e0;
                    g_eidx[N + token] = e1;
                    g_pval[token]     = inv;
                    g_pval[N + token] = expf(b1 - b0) * inv;
                }
            }
        }
        __syncwarp();
        if (lane == 0) {
            __threadfence();
            atomicAdd(&g_done_router, 1u);
        }
        return;
    }

    // ======================= CTA 0: rank then scatter =======================
    if (tid < N_EXP) running[tid] = 0;

    if (tid == 0) {
        while (atomicAdd(&g_done_router, 0u) < (unsigned)R_TARGET) { }
        atomicSub(&g_done_router, (unsigned)R_TARGET);   // reset for replay
        __threadfence();
    }
    __syncthreads();

    // ---- ordered per-expert rank scan (k-major, token order) ----
    const int total = 2 * N;
    const int rounds = (total + BLOCK - 1) / BLOCK;
    for (int rd = 0; rd < rounds; rd++) {
        const int i = rd * BLOCK + tid;
        const int e = (i < total) ? g_eidx[i] : -1;

        if (tid < N_EXP * 32) ((int*)warpcnt)[tid] = 0;
        __syncthreads();

        unsigned m = __match_any_sync(0xFFFFFFFFu, e);
        int lrank  = __popc(m & ((1u << lane) - 1u));
        int leader = __ffs(m) - 1;
        if (e >= 0 && lane == leader)
            warpcnt[e][warp] = __popc(m);
        __syncthreads();

        if (warp < N_EXP) {
            int runv = running[warp];
            int v = warpcnt[warp][lane];
            int s = v;
#pragma unroll
            for (int off = 1; off < 32; off <<= 1) {
                int u = __shfl_up_sync(0xFFFFFFFFu, s, off);
                if (lane >= off) s += u;
            }
            basesh[warp][lane] = runv + s - v;
            if (lane == 31) running[warp] = runv + s;
        }
        __syncthreads();

        if (e >= 0)
            g_rank[i] = basesh[e][warp] + lrank;
        __syncthreads();
    }

    // used_capacity lives outside the fill region — write now.
    if (tid < N_EXP) {
        int uc = running[tid];
        if (uc > C) uc = C;
        out[tid] = (float)uc;
    }

    // ---- wait for all fill warps, then scatter ----
    if (tid == 0) {
        while (atomicAdd(&g_done_fill, 0u) < (unsigned)F_TARGET) { }
        atomicSub(&g_done_fill, (unsigned)F_TARGET);     // reset for replay
        __threadfence();
    }
    __syncthreads();

    // tail floats not covered by float4 fill (none when C even, but safe)
    {
        long long done = 8 + (fillF4 << 2);
        for (long long i = done + tid; i < out_elems; i += BLOCK)
            out[i] = 0.0f;
    }

    for (int i = tid; i < total; i += BLOCK) {
        int r = g_rank[i];
        if (r < C) {
            int e = g_eidx[i];
            int k = (i >= N) ? 1 : 0;
            int n = i - k * N;
            long long pos = ((long long)n * N_EXP + e) * (long long)C + r;
            out[8 + pos]         = g_pval[i];
            out[8 + rowsC + pos] = 1.0f;
        }
    }
}

// ---------------------------------------------------------------------------
extern "C" void kernel_launch(void* const* d_in, const int* in_sizes, int n_in,
                              void* d_out, int out_size)
{
    const float* x   = (const float*)d_in[0];
    const float* w_g = (const float*)d_in[1];
    float* out = (float*)d_out;

    const int D = in_sizes[1] / N_EXP;   // 1024
    const int N = in_sizes[0] / D;       // 4096 tokens

    int C = (int)floorf(2.0f * 1.25f * (float)N / (float)N_EXP);
    C += (C & 1);
    if (C < 4) C = 4;

    router_fused_kernel<<<GRID, BLOCK>>>(x, w_g, out, N, C,
                                         (long long)out_size);
}

// round 12
// speedup vs baseline: 1.1158x; 1.1081x over previous
#include <cuda_runtime.h>
#include <cuda_bf16.h>
#include <math.h>

// ---------------------------------------------------------------------------
// MoE router (TOP_K=2, N_EXP=8).
// Output (float32): [0..8) used_capacity | [8..8+R) cb_weight | [8+R..8+2R) sec_mask
//   where R = N*8*C.
//
// Kernel 1 (persistent, 148 CTAs x 1024, one per SM):
//   CTA 1..147: warps 0..13  = router (2 tokens/warp, smem w_g)
//               warps 14..31 = zero-fill (grid-stride interleaved STG.128)
//   CTA 0     : spin-join router -> ordered rank scan -> used_capacity.
//   NO scatter here: R10/R11 showed a single-CTA scatter tail costs ~25us.
// Kernel 2 (wide grid): scatter 2N nonzeros (kernel boundary = global sync
//   between fill and scatter).
// g_done_router: release-fence + atomicAdd; the single waiter (CTA 0)
// subtracts the target after observing it => replays start from zero.
// ---------------------------------------------------------------------------

#define N_EXP 8
#define MAXN 65536
#define GRID 148
#define BLOCK 1024
#define RW_PER_CTA 14              // router warps per worker CTA
#define FW_PER_CTA 18              // fill warps per worker CTA
#define R_TARGET ((GRID - 1) * RW_PER_CTA)          // 2058
#define F_THREADS ((long long)(GRID - 1) * FW_PER_CTA * 32)  // 84672

__device__ int          g_eidx[2 * MAXN];
__device__ float        g_pval[2 * MAXN];
__device__ int          g_rank[2 * MAXN];
__device__ int          g_total[N_EXP];
__device__ unsigned int g_done_router;   // zero-init; self-resetting

__global__ void __launch_bounds__(BLOCK, 1) fused_kernel(
    const float* __restrict__ x, const float* __restrict__ w_g,
    float* __restrict__ out, int N, int C, long long out_elems)
{
    __shared__ float4 ws[N_EXP * 256];          // 32KB w_g (D=1024)
    __shared__ int warpcnt[N_EXP][32];
    __shared__ int basesh[N_EXP][32];
    __shared__ int running[N_EXP];

    const int tid  = threadIdx.x;
    const int warp = tid >> 5;
    const int lane = tid & 31;
    const int b    = blockIdx.x;

    const long long fillF4 = (out_elems - 8) >> 2;       // float4 count
    float4* const   fill4  = reinterpret_cast<float4*>(out + 8);

    if (b != 0) {
        if (warp >= RW_PER_CTA) {
            // ========== FILL WARPS: grid-stride interleaved zeroing ==========
            const long long ftid =
                (long long)(b - 1) * FW_PER_CTA * 32 +
                (long long)(warp - RW_PER_CTA) * 32 + lane;
            const float4 z = make_float4(0.f, 0.f, 0.f, 0.f);

            long long i = ftid;
            const long long step4 = 4 * F_THREADS;
            for (; i + 3 * F_THREADS < fillF4; i += step4) {
                fill4[i]                 = z;
                fill4[i + F_THREADS]     = z;
                fill4[i + 2 * F_THREADS] = z;
                fill4[i + 3 * F_THREADS] = z;
            }
            for (; i < fillF4; i += F_THREADS)
                fill4[i] = z;
            return;
        }

        // ============== ROUTER WARPS: 2 tokens per warp ==============
        const float4* wg4 = reinterpret_cast<const float4*>(w_g);
        const int rt = warp * 32 + lane;                 // 0..447
        for (int idx = rt; idx < N_EXP * 256; idx += RW_PER_CTA * 32)
            ws[idx] = wg4[idx];
        asm volatile("bar.sync 1, %0;" :: "r"(RW_PER_CTA * 32) : "memory");

        const int rw = (b - 1) * RW_PER_CTA + warp;

        for (int tok0 = rw * 2; tok0 < N; tok0 += R_TARGET * 2) {
            const float4* x4 =
                reinterpret_cast<const float4*>(x) + (size_t)tok0 * 256;
            const bool full = (tok0 + 1) < N;

            float acc[2][N_EXP];
#pragma unroll
            for (int t = 0; t < 2; t++)
#pragma unroll
                for (int e = 0; e < N_EXP; e++) acc[t][e] = 0.0f;

#pragma unroll
            for (int j = 0; j < 8; j++) {
                float4 xv[2];
#pragma unroll
                for (int t = 0; t < 2; t++)
                    xv[t] = (full || (tok0 + t) < N)
                          ? x4[t * 256 + j * 32 + lane]
                          : make_float4(0.f, 0.f, 0.f, 0.f);
#pragma unroll
                for (int e = 0; e < N_EXP; e++) {
                    float4 wv = ws[e * 256 + j * 32 + lane];
#pragma unroll
                    for (int t = 0; t < 2; t++)
                        acc[t][e] += xv[t].x * wv.x + xv[t].y * wv.y +
                                     xv[t].z * wv.z + xv[t].w * wv.w;
                }
            }

#pragma unroll
            for (int off = 16; off > 0; off >>= 1)
#pragma unroll
                for (int t = 0; t < 2; t++)
#pragma unroll
                    for (int e = 0; e < N_EXP; e++)
                        acc[t][e] += __shfl_xor_sync(0xFFFFFFFFu,
                                                     acc[t][e], off);

            if (lane < 2) {
                const int t = lane;
                const int token = tok0 + t;
                if (token < N) {
                    float a[N_EXP];
#pragma unroll
                    for (int e = 0; e < N_EXP; e++) a[e] = acc[t][e];

                    int e0 = 0; float b0 = a[0];
#pragma unroll
                    for (int e = 1; e < N_EXP; e++)
                        if (a[e] > b0) { b0 = a[e]; e0 = e; }
                    int e1 = (e0 == 0) ? 1 : 0; float b1 = a[e1];
#pragma unroll
                    for (int e = 0; e < N_EXP; e++)
                        if (e != e0 && a[e] > b1) { b1 = a[e]; e1 = e; }

                    float sum = 0.0f;
#pragma unroll
                    for (int e = 0; e < N_EXP; e++)
                        sum += expf(a[e] - b0);
                    float inv = 1.0f / sum;

                    g_eidx[token]     = e0;
                    g_eidx[N + token] = e1;
                    g_pval[token]     = inv;
                    g_pval[N + token] = expf(b1 - b0) * inv;
                }
            }
        }
        __syncwarp();
        if (lane == 0) {
            __threadfence();
            atomicAdd(&g_done_router, 1u);
        }
        return;
    }

    // =================== CTA 0: rank scan + used_capacity ===================
    if (tid < N_EXP) running[tid] = 0;

    if (tid == 0) {
        while (atomicAdd(&g_done_router, 0u) < (unsigned)R_TARGET) { }
        atomicSub(&g_done_router, (unsigned)R_TARGET);   // reset for replay
        __threadfence();
    }
    __syncthreads();

    const int total = 2 * N;
    const int rounds = (total + BLOCK - 1) / BLOCK;
    for (int rd = 0; rd < rounds; rd++) {
        const int i = rd * BLOCK + tid;
        const int e = (i < total) ? g_eidx[i] : -1;

        if (tid < N_EXP * 32) ((int*)warpcnt)[tid] = 0;
        __syncthreads();

        unsigned m = __match_any_sync(0xFFFFFFFFu, e);
        int lrank  = __popc(m & ((1u << lane) - 1u));
        int leader = __ffs(m) - 1;
        if (e >= 0 && lane == leader)
            warpcnt[e][warp] = __popc(m);
        __syncthreads();

        if (warp < N_EXP) {
            int runv = running[warp];
            int v = warpcnt[warp][lane];
            int s = v;
#pragma unroll
            for (int off = 1; off < 32; off <<= 1) {
                int u = __shfl_up_sync(0xFFFFFFFFu, s, off);
                if (lane >= off) s += u;
            }
            basesh[warp][lane] = runv + s - v;
            if (lane == 31) running[warp] = runv + s;
        }
        __syncthreads();

        if (e >= 0)
            g_rank[i] = basesh[e][warp] + lrank;
        __syncthreads();
    }

    // used_capacity (out[0..8) is outside the fill region)
    if (tid < N_EXP) {
        int uc = running[tid];
        if (uc > C) uc = C;
        out[tid] = (float)uc;
        g_total[tid] = uc;
    }

    // tail floats not covered by float4 fill (none when C even, but safe)
    {
        long long done = 8 + (((out_elems - 8) >> 2) << 2);
        for (long long i = done + tid; i < out_elems; i += BLOCK)
            out[i] = 0.0f;
    }
}

// ---------------------------------------------------------------------------
// Kernel 2: wide-grid scatter. One thread per routed entry: at most 2 stores
// into the (already-zeroed) output.
// ---------------------------------------------------------------------------
__global__ void __launch_bounds__(256) scatter_kernel(
    float* __restrict__ out, int N, int C)
{
    const int i = blockIdx.x * blockDim.x + threadIdx.x;
    const int total = 2 * N;
    const long long rowsC = (long long)N * N_EXP * (long long)C;

    if (i < total) {
        int r = g_rank[i];
        if (r < C) {
            int e = g_eidx[i];
            int k = (i >= N) ? 1 : 0;
            int n = i - k * N;
            long long pos = ((long long)n * N_EXP + e) * (long long)C + r;
            out[8 + pos]         = g_pval[i];
            out[8 + rowsC + pos] = 1.0f;
        }
    }
}

// ---------------------------------------------------------------------------
extern "C" void kernel_launch(void* const* d_in, const int* in_sizes, int n_in,
                              void* d_out, int out_size)
{
    const float* x   = (const float*)d_in[0];
    const float* w_g = (const float*)d_in[1];
    float* out = (float*)d_out;

    const int D = in_sizes[1] / N_EXP;   // 1024
    const int N = in_sizes[0] / D;       // 4096 tokens

    int C = (int)floorf(2.0f * 1.25f * (float)N / (float)N_EXP);
    C += (C & 1);
    if (C < 4) C = 4;

    // 1) fused: fill (336MB) overlapped with router + ordered rank scan
    fused_kernel<<<GRID, BLOCK>>>(x, w_g, out, N, C, (long long)out_size);

    // 2) wide-grid scatter of the 2N nonzeros
    int sblocks = (2 * N + 255) / 256;
    scatter_kernel<<<sblocks, 256>>>(out, N, C);
}